// round 1
// baseline (speedup 1.0000x reference)
#include <cuda_runtime.h>
#include <math.h>

#define NNODES 20000
#define NEDGES 640000
#define NSZ 128
#define ESZ 20
#define CUTF 5.0f

// scalar_output scratch: [NNODES, 384]
__device__ float g_so[NNODES * 384];

// ---------------------------------------------------------------------------
// float4 helpers
// ---------------------------------------------------------------------------
__device__ __forceinline__ float4 f4_fma_s(float a, float4 w, float4 c) {
    c.x = fmaf(a, w.x, c.x); c.y = fmaf(a, w.y, c.y);
    c.z = fmaf(a, w.z, c.z); c.w = fmaf(a, w.w, c.w);
    return c;
}
__device__ __forceinline__ float4 f4_mul(float4 a, float4 b) {
    return make_float4(a.x*b.x, a.y*b.y, a.z*b.z, a.w*b.w);
}
__device__ __forceinline__ float4 f4_scale(float4 a, float s) {
    return make_float4(a.x*s, a.y*s, a.z*s, a.w*s);
}
// acc = xv * g + s * f
__device__ __forceinline__ float4 f4_msg(float4 xv, float4 g, float s, float4 f) {
    return make_float4(fmaf(xv.x, g.x, s*f.x), fmaf(xv.y, g.y, s*f.y),
                       fmaf(xv.z, g.z, s*f.z), fmaf(xv.w, g.w, s*f.w));
}
__device__ __forceinline__ void red4(float* p, float4 v) {
    asm volatile("red.global.add.v4.f32 [%0], {%1, %2, %3, %4};"
                 :: "l"(p), "f"(v.x), "f"(v.y), "f"(v.z), "f"(v.w) : "memory");
}

// ---------------------------------------------------------------------------
// Kernel 1: scalar_output = silu(x @ W1 + b1) @ W2 + b2      -> g_so
// Block: 128 threads, NB nodes per block. smem: W tile + X + H (dynamic)
// ---------------------------------------------------------------------------
#define NB 16

__global__ void __launch_bounds__(128) node_mlp(
    const float* __restrict__ nss, const float* __restrict__ W1,
    const float* __restrict__ b1, const float* __restrict__ W2,
    const float* __restrict__ b2)
{
    extern __shared__ float sm[];
    float* sW = sm;                 // 128*128
    float* sX = sm + 16384;         // NB*128
    float* sH = sX + NB * 128;      // NB*128
    const int tid = threadIdx.x;
    const int n0 = blockIdx.x * NB;

    for (int i = tid; i < NB * 128; i += 128) {
        int n = n0 + (i >> 7);
        sX[i] = (n < NNODES) ? nss[n * NSZ + (i & 127)] : 0.f;
    }
    for (int i = tid; i < 16384; i += 128) sW[i] = W1[i];
    __syncthreads();

    float acc[NB];
    #pragma unroll
    for (int n = 0; n < NB; n++) acc[n] = 0.f;
    #pragma unroll 4
    for (int k = 0; k < 128; k++) {
        float w = sW[k * 128 + tid];
        #pragma unroll
        for (int n = 0; n < NB; n++) acc[n] = fmaf(sX[n * 128 + k], w, acc[n]);
    }
    {
        float bb = b1[tid];
        #pragma unroll
        for (int n = 0; n < NB; n++) {
            float h = acc[n] + bb;
            sH[n * 128 + tid] = h / (1.f + __expf(-h));   // silu
        }
    }
    __syncthreads();

    for (int t = 0; t < 3; t++) {
        for (int i = tid; i < 16384; i += 128) {
            int k = i >> 7, j = i & 127;
            sW[i] = W2[k * 384 + t * 128 + j];
        }
        __syncthreads();
        #pragma unroll
        for (int n = 0; n < NB; n++) acc[n] = 0.f;
        #pragma unroll 4
        for (int k = 0; k < 128; k++) {
            float w = sW[k * 128 + tid];
            #pragma unroll
            for (int n = 0; n < NB; n++) acc[n] = fmaf(sH[n * 128 + k], w, acc[n]);
        }
        float b = b2[t * 128 + tid];
        #pragma unroll
        for (int n = 0; n < NB; n++) {
            int node = n0 + n;
            if (node < NNODES) g_so[node * 384 + t * 128 + tid] = acc[n] + b;
        }
        __syncthreads();
    }
}

// ---------------------------------------------------------------------------
// Kernel 2: out = [node_state_scalar | node_state_vector]  (base for += msgs)
// ---------------------------------------------------------------------------
__global__ void __launch_bounds__(256) init_out(
    float4* __restrict__ out, const float4* __restrict__ nss,
    const float4* __restrict__ nsv)
{
    const int S4 = NNODES * NSZ / 4;          // 640000
    const int T4 = S4 + NNODES * 384 / 4;     // 2560000
    int i = blockIdx.x * blockDim.x + threadIdx.x;
    if (i < S4)      out[i] = nss[i];
    else if (i < T4) out[i] = nsv[i - S4];
}

// ---------------------------------------------------------------------------
// Kernel 3: per-edge filter + messages + vector-RED scatter
// 256 threads (8 warps). W_filter + b_filter in smem (loaded once per block).
// Each warp processes 2 edges at a time (amortizes smem W reads).
// Lane owns 4 consecutive columns in each 128-col group -> float4 everywhere.
// ---------------------------------------------------------------------------
__global__ void __launch_bounds__(256) edge_kernel(
    const float* __restrict__ nss, const float* __restrict__ nsv,
    const float* __restrict__ edge_state, const float* __restrict__ edge_vector,
    const float* __restrict__ edge_distance, const int* __restrict__ edges,
    const float* __restrict__ Wf, const float* __restrict__ bf,
    float* __restrict__ out)
{
    __shared__ __align__(16) float sWf[ESZ * 384];
    __shared__ __align__(16) float sbf[384];
    const int tid = threadIdx.x;
    for (int i = tid; i < ESZ * 384; i += 256) sWf[i] = Wf[i];
    for (int i = tid; i < 384; i += 256) sbf[i] = bf[i];
    __syncthreads();

    const int lane  = tid & 31;
    const int warp  = tid >> 5;
    const int gwarp = blockIdx.x * 8 + warp;
    const int nwarp = gridDim.x * 8;
    const int c0    = lane * 4;

    float* __restrict__ outS = out;
    float* __restrict__ outV = out + (size_t)NNODES * NSZ;

    const float4 bsv = *(const float4*)&sbf[c0];
    const float4 bev = *(const float4*)&sbf[128 + c0];
    const float4 bns = *(const float4*)&sbf[256 + c0];

    for (int e0 = gwarp * 2; e0 < NEDGES; e0 += nwarp * 2) {
        const int e1 = e0 + 1;   // NEDGES even, stride even -> always valid

        float esA[ESZ], esB[ESZ];
        #pragma unroll
        for (int k = 0; k < ESZ; k++) {
            esA[k] = __ldg(&edge_state[e0 * ESZ + k]);
            esB[k] = __ldg(&edge_state[e1 * ESZ + k]);
        }

        float4 aSV = bsv, aEV = bev, aNS = bns;
        float4 cSV = bsv, cEV = bev, cNS = bns;
        #pragma unroll
        for (int k = 0; k < ESZ; k++) {
            const float4 wsv = *(const float4*)&sWf[k * 384 + c0];
            const float4 wev = *(const float4*)&sWf[k * 384 + 128 + c0];
            const float4 wns = *(const float4*)&sWf[k * 384 + 256 + c0];
            aSV = f4_fma_s(esA[k], wsv, aSV);
            aEV = f4_fma_s(esA[k], wev, aEV);
            aNS = f4_fma_s(esA[k], wns, aNS);
            cSV = f4_fma_s(esB[k], wsv, cSV);
            cEV = f4_fma_s(esB[k], wev, cEV);
            cNS = f4_fma_s(esB[k], wns, cNS);
        }

        #pragma unroll
        for (int which = 0; which < 2; which++) {
            const int e = which ? e1 : e0;
            float4 fSV = which ? cSV : aSV;
            float4 fEV = which ? cEV : aEV;
            float4 fNS = which ? cNS : aNS;

            const int src = __ldg(&edges[2 * e]);
            const int dst = __ldg(&edges[2 * e + 1]);

            const float d = __ldg(&edge_distance[e]);
            const float cu = (d < CUTF)
                ? 0.5f * (__cosf(3.14159265358979f * d * (1.0f / CUTF)) + 1.0f)
                : 0.0f;

            const float v0 = __ldg(&edge_vector[3 * e]);
            const float v1 = __ldg(&edge_vector[3 * e + 1]);
            const float v2 = __ldg(&edge_vector[3 * e + 2]);
            const float nrm = sqrtf(v0 * v0 + v1 * v1 + v2 * v2);
            const float inv = 1.0f / fmaxf(nrm, 1e-12f);
            const float en0 = v0 * inv, en1 = v1 * inv, en2 = v2 * inv;

            fSV = f4_scale(fSV, cu);
            fEV = f4_scale(fEV, cu);
            fNS = f4_scale(fNS, cu);

            const float* so = &g_so[(size_t)src * 384];
            const float4 soSV = *(const float4*)&so[c0];
            const float4 soEV = *(const float4*)&so[128 + c0];
            const float4 soNS = *(const float4*)&so[256 + c0];

            const float4 foSV = f4_mul(fSV, soSV);   // gate_state_vector
            const float4 foEV = f4_mul(fEV, soEV);   // gate_edge_vector
            const float4 foNS = f4_mul(fNS, soNS);   // gate_node_state

            // scalar message
            const float4 xs = *(const float4*)&nss[(size_t)src * NSZ + c0];
            red4(&outS[(size_t)dst * NSZ + c0], f4_mul(xs, foNS));

            // vector messages (3 spatial dims)
            const float* nv = &nsv[(size_t)src * 384];
            float* ov = &outV[(size_t)dst * 384];
            {
                const float4 xv = *(const float4*)&nv[c0];
                red4(&ov[c0], f4_msg(xv, foSV, en0, foEV));
            }
            {
                const float4 xv = *(const float4*)&nv[128 + c0];
                red4(&ov[128 + c0], f4_msg(xv, foSV, en1, foEV));
            }
            {
                const float4 xv = *(const float4*)&nv[256 + c0];
                red4(&ov[256 + c0], f4_msg(xv, foSV, en2, foEV));
            }
        }
    }
}

// ---------------------------------------------------------------------------
extern "C" void kernel_launch(void* const* d_in, const int* in_sizes, int n_in,
                              void* d_out, int out_size)
{
    const float* nss           = (const float*)d_in[0];
    const float* nsv           = (const float*)d_in[1];
    const float* edge_state    = (const float*)d_in[2];
    const float* edge_vector   = (const float*)d_in[3];
    const float* edge_distance = (const float*)d_in[4];
    const int*   edges         = (const int*)d_in[5];
    const float* W_filter      = (const float*)d_in[6];
    const float* b_filter      = (const float*)d_in[7];
    const float* W1            = (const float*)d_in[8];
    const float* b1            = (const float*)d_in[9];
    const float* W2            = (const float*)d_in[10];
    const float* b2            = (const float*)d_in[11];
    float* out = (float*)d_out;

    // node MLP: dynamic smem = (16384 + 2*NB*128) * 4 = 80 KB
    const int smem1 = (16384 + 2 * NB * 128) * sizeof(float);
    cudaFuncSetAttribute(node_mlp, cudaFuncAttributeMaxDynamicSharedMemorySize, smem1);

    node_mlp<<<(NNODES + NB - 1) / NB, 128, smem1>>>(nss, W1, b1, W2, b2);
    init_out<<<10000, 256>>>((float4*)out, (const float4*)nss, (const float4*)nsv);
    edge_kernel<<<592, 256>>>(nss, nsv, edge_state, edge_vector, edge_distance,
                              edges, W_filter, b_filter, out);
}

// round 2
// speedup vs baseline: 1.5358x; 1.5358x over previous
#include <cuda_runtime.h>
#include <math.h>

#define NNODES 20000
#define NEDGES 640000
#define NSZ 128
#define ESZ 20
#define CUTF 5.0f

// scalar_output scratch: [NNODES, 384]
__device__ float g_so[NNODES * 384];

typedef unsigned long long u64;

// ---------------------------------------------------------------------------
// f32x2 packed helpers (Blackwell FFMA2 path)
// ---------------------------------------------------------------------------
__device__ __forceinline__ void fma2(u64& d, u64 a, u64 b) {
    asm("fma.rn.f32x2 %0, %1, %2, %0;" : "+l"(d) : "l"(a), "l"(b));
}
__device__ __forceinline__ u64 pack2(float x) {
    u64 r; asm("mov.b64 %0, {%1, %1};" : "=l"(r) : "f"(x)); return r;
}
__device__ __forceinline__ float2 unpack2(u64 a) {
    float2 f; asm("mov.b64 {%0, %1}, %2;" : "=f"(f.x), "=f"(f.y) : "l"(a));
    return f;
}

// ---------------------------------------------------------------------------
// float4 helpers
// ---------------------------------------------------------------------------
__device__ __forceinline__ float4 f4_fma_s(float a, float4 w, float4 c) {
    c.x = fmaf(a, w.x, c.x); c.y = fmaf(a, w.y, c.y);
    c.z = fmaf(a, w.z, c.z); c.w = fmaf(a, w.w, c.w);
    return c;
}
__device__ __forceinline__ float4 f4_mul(float4 a, float4 b) {
    return make_float4(a.x*b.x, a.y*b.y, a.z*b.z, a.w*b.w);
}
// acc = xv * g + s * f
__device__ __forceinline__ float4 f4_msg(float4 xv, float4 g, float s, float4 f) {
    return make_float4(fmaf(xv.x, g.x, s*f.x), fmaf(xv.y, g.y, s*f.y),
                       fmaf(xv.z, g.z, s*f.z), fmaf(xv.w, g.w, s*f.w));
}
__device__ __forceinline__ void red4(float* p, float4 v) {
    asm volatile("red.global.add.v4.f32 [%0], {%1, %2, %3, %4};"
                 :: "l"(p), "f"(v.x), "f"(v.y), "f"(v.z), "f"(v.w) : "memory");
}

// ---------------------------------------------------------------------------
// Kernel 1: scalar_output = silu(x @ W1 + b1) @ W2 + b2 -> g_so
//           + copies this block's slice of [nss | nsv] into out (init fold)
// 256 threads, 64 nodes/block. Each thread: 8 nodes x 4 cols, vectorized LDS.
// ---------------------------------------------------------------------------
#define NB 64

__global__ void __launch_bounds__(256) node_mlp(
    const float4* __restrict__ nss4, const float4* __restrict__ nsv4,
    const float* __restrict__ W1, const float* __restrict__ b1,
    const float* __restrict__ W2, const float* __restrict__ b2,
    float4* __restrict__ out)
{
    extern __shared__ float sm[];
    float* sW = sm;              // 16384 floats
    float* sX = sm + 16384;      // 8192
    float* sH = sX + 8192;       // 8192

    const int tid = threadIdx.x;
    const int n0 = blockIdx.x * NB;

    // --- fold: out base copy for this block's nodes ---
    {
        const float4* nssb = nss4 + (size_t)n0 * 32;
        float4* outS = out + (size_t)n0 * 32;
        for (int i = tid; i < NB * 32; i += 256)
            if (n0 + (i >> 5) < NNODES) outS[i] = nssb[i];
        const float4* nsvb = nsv4 + (size_t)n0 * 96;
        float4* outV = out + (size_t)NNODES * 32 + (size_t)n0 * 96;
        for (int i = tid; i < NB * 96; i += 256)
            if (n0 + i / 96 < NNODES) outV[i] = nsvb[i];
    }

    // --- load X tile + W1 ---
    for (int i = tid; i < NB * 32; i += 256) {
        int n = n0 + (i >> 5);
        ((float4*)sX)[i] = (n < NNODES) ? nss4[(size_t)n * 32 + (i & 31)]
                                        : make_float4(0.f, 0.f, 0.f, 0.f);
    }
    for (int i = tid; i < 4096; i += 256)
        ((float4*)sW)[i] = ((const float4*)W1)[i];
    __syncthreads();

    const int tx = tid & 31, ty = tid >> 5;
    const int c0 = tx * 4;

    float4 acc[8];

    // --- phase 1: H = silu(X @ W1 + b1) ---
    #pragma unroll
    for (int i = 0; i < 8; i++) acc[i] = make_float4(0.f, 0.f, 0.f, 0.f);
    #pragma unroll 8
    for (int k = 0; k < 128; k += 4) {
        const float4 w0 = *(const float4*)&sW[(k + 0) * 128 + c0];
        const float4 w1 = *(const float4*)&sW[(k + 1) * 128 + c0];
        const float4 w2 = *(const float4*)&sW[(k + 2) * 128 + c0];
        const float4 w3 = *(const float4*)&sW[(k + 3) * 128 + c0];
        #pragma unroll
        for (int i = 0; i < 8; i++) {
            const int ln = ty * 8 + i;
            const float4 xv = *(const float4*)&sX[ln * 128 + k];
            acc[i] = f4_fma_s(xv.x, w0, acc[i]);
            acc[i] = f4_fma_s(xv.y, w1, acc[i]);
            acc[i] = f4_fma_s(xv.z, w2, acc[i]);
            acc[i] = f4_fma_s(xv.w, w3, acc[i]);
        }
    }
    {
        const float4 bb = __ldg((const float4*)&b1[c0]);
        #pragma unroll
        for (int i = 0; i < 8; i++) {
            const int ln = ty * 8 + i;
            float4 h = make_float4(acc[i].x + bb.x, acc[i].y + bb.y,
                                   acc[i].z + bb.z, acc[i].w + bb.w);
            h.x = h.x / (1.f + __expf(-h.x));
            h.y = h.y / (1.f + __expf(-h.y));
            h.z = h.z / (1.f + __expf(-h.z));
            h.w = h.w / (1.f + __expf(-h.w));
            *(float4*)&sH[ln * 128 + c0] = h;
        }
    }

    // --- phase 2: g_so tiles = H @ W2 + b2 (3 x 128 cols) ---
    for (int t = 0; t < 3; t++) {
        __syncthreads();
        for (int i = tid; i < 4096; i += 256) {
            int k = i >> 5, jj = i & 31;
            ((float4*)sW)[i] = *(const float4*)&W2[(size_t)k * 384 + t * 128 + jj * 4];
        }
        __syncthreads();
        #pragma unroll
        for (int i = 0; i < 8; i++) acc[i] = make_float4(0.f, 0.f, 0.f, 0.f);
        #pragma unroll 8
        for (int k = 0; k < 128; k += 4) {
            const float4 w0 = *(const float4*)&sW[(k + 0) * 128 + c0];
            const float4 w1 = *(const float4*)&sW[(k + 1) * 128 + c0];
            const float4 w2 = *(const float4*)&sW[(k + 2) * 128 + c0];
            const float4 w3 = *(const float4*)&sW[(k + 3) * 128 + c0];
            #pragma unroll
            for (int i = 0; i < 8; i++) {
                const int ln = ty * 8 + i;
                const float4 xv = *(const float4*)&sH[ln * 128 + k];
                acc[i] = f4_fma_s(xv.x, w0, acc[i]);
                acc[i] = f4_fma_s(xv.y, w1, acc[i]);
                acc[i] = f4_fma_s(xv.z, w2, acc[i]);
                acc[i] = f4_fma_s(xv.w, w3, acc[i]);
            }
        }
        const float4 bb = __ldg((const float4*)&b2[t * 128 + c0]);
        #pragma unroll
        for (int i = 0; i < 8; i++) {
            const int ln = ty * 8 + i;
            const int n = n0 + ln;
            if (n < NNODES) {
                float4 r = make_float4(acc[i].x + bb.x, acc[i].y + bb.y,
                                       acc[i].z + bb.z, acc[i].w + bb.w);
                *(float4*)&g_so[(size_t)n * 384 + t * 128 + c0] = r;
            }
        }
    }
}

// ---------------------------------------------------------------------------
// Kernel 2: per-edge filter (f32x2 FMA, 4 edges/warp) + messages + RED scatter
// 128 threads (4 warps). W_filter/b_filter in smem; edge_state staged per warp.
// ---------------------------------------------------------------------------
#define EPW 4

__global__ void __launch_bounds__(128) edge_kernel(
    const float* __restrict__ nss, const float* __restrict__ nsv,
    const float* __restrict__ edge_state, const float* __restrict__ edge_vector,
    const float* __restrict__ edge_distance, const int* __restrict__ edges,
    const float* __restrict__ Wf, const float* __restrict__ bf,
    float* __restrict__ out)
{
    __shared__ __align__(16) float sWf[ESZ * 384];
    __shared__ __align__(16) float sbf[384];
    __shared__ __align__(16) float sES[4][EPW * ESZ];

    const int tid = threadIdx.x;
    for (int i = tid; i < ESZ * 384 / 4; i += 128)
        ((float4*)sWf)[i] = ((const float4*)Wf)[i];
    for (int i = tid; i < 96; i += 128)
        ((float4*)sbf)[i] = ((const float4*)bf)[i];
    __syncthreads();

    const int lane  = tid & 31;
    const int warp  = tid >> 5;
    const int gwarp = blockIdx.x * 4 + warp;
    const int nwarp = gridDim.x * 4;
    const int c0    = lane * 4;

    float* __restrict__ outS = out;
    float* __restrict__ outV = out + (size_t)NNODES * NSZ;
    float* myES = sES[warp];

    const ulonglong2 bS = *(const ulonglong2*)&sbf[c0];
    const ulonglong2 bE = *(const ulonglong2*)&sbf[128 + c0];
    const ulonglong2 bN = *(const ulonglong2*)&sbf[256 + c0];

    for (int e0 = gwarp * EPW; e0 < NEDGES; e0 += nwarp * EPW) {
        // stage edge_state for EPW edges into per-warp smem
        __syncwarp();
        if (lane < EPW * 5) {
            int e = lane / 5, c = lane % 5;
            *(float4*)&myES[e * ESZ + c * 4] =
                __ldg((const float4*)&edge_state[(size_t)(e0 + e) * ESZ] + c);
        }
        __syncwarp();

        // filter GEMM: acc = bf + es @ Wf  (packed f32x2)
        u64 acc[EPW][6];
        #pragma unroll
        for (int e = 0; e < EPW; e++) {
            acc[e][0] = bS.x; acc[e][1] = bS.y;
            acc[e][2] = bE.x; acc[e][3] = bE.y;
            acc[e][4] = bN.x; acc[e][5] = bN.y;
        }
        #pragma unroll
        for (int k = 0; k < ESZ; k++) {
            const ulonglong2 wS = *(const ulonglong2*)&sWf[k * 384 + c0];
            const ulonglong2 wE = *(const ulonglong2*)&sWf[k * 384 + 128 + c0];
            const ulonglong2 wN = *(const ulonglong2*)&sWf[k * 384 + 256 + c0];
            #pragma unroll
            for (int e = 0; e < EPW; e++) {
                const u64 s2 = pack2(myES[e * ESZ + k]);
                fma2(acc[e][0], s2, wS.x); fma2(acc[e][1], s2, wS.y);
                fma2(acc[e][2], s2, wE.x); fma2(acc[e][3], s2, wE.y);
                fma2(acc[e][4], s2, wN.x); fma2(acc[e][5], s2, wN.y);
            }
        }

        // per-edge gather + message + scatter
        #pragma unroll
        for (int e = 0; e < EPW; e++) {
            const int ed  = e0 + e;
            const int src = __ldg(&edges[2 * ed]);
            const int dst = __ldg(&edges[2 * ed + 1]);

            const float d = __ldg(&edge_distance[ed]);
            const float cu = (d < CUTF)
                ? 0.5f * (__cosf(3.14159265358979f * d * (1.0f / CUTF)) + 1.0f)
                : 0.0f;

            const float v0 = __ldg(&edge_vector[3 * ed]);
            const float v1 = __ldg(&edge_vector[3 * ed + 1]);
            const float v2 = __ldg(&edge_vector[3 * ed + 2]);
            const float nrm = sqrtf(v0 * v0 + v1 * v1 + v2 * v2);
            const float inv = 1.0f / fmaxf(nrm, 1e-12f);
            const float en0 = v0 * inv, en1 = v1 * inv, en2 = v2 * inv;

            float2 p0 = unpack2(acc[e][0]), p1 = unpack2(acc[e][1]);
            float2 p2 = unpack2(acc[e][2]), p3 = unpack2(acc[e][3]);
            float2 p4 = unpack2(acc[e][4]), p5 = unpack2(acc[e][5]);
            float4 fSV = make_float4(p0.x * cu, p0.y * cu, p1.x * cu, p1.y * cu);
            float4 fEV = make_float4(p2.x * cu, p2.y * cu, p3.x * cu, p3.y * cu);
            float4 fNS = make_float4(p4.x * cu, p4.y * cu, p5.x * cu, p5.y * cu);

            const float* so = &g_so[(size_t)src * 384];
            const float4 soSV = *(const float4*)&so[c0];
            const float4 soEV = *(const float4*)&so[128 + c0];
            const float4 soNS = *(const float4*)&so[256 + c0];

            const float4 foSV = f4_mul(fSV, soSV);   // gate_state_vector
            const float4 foEV = f4_mul(fEV, soEV);   // gate_edge_vector
            const float4 foNS = f4_mul(fNS, soNS);   // gate_node_state

            // scalar message
            const float4 xs = *(const float4*)&nss[(size_t)src * NSZ + c0];
            red4(&outS[(size_t)dst * NSZ + c0], f4_mul(xs, foNS));

            // vector messages
            const float* nv = &nsv[(size_t)src * 384];
            float* ov = &outV[(size_t)dst * 384];
            {
                const float4 xv = *(const float4*)&nv[c0];
                red4(&ov[c0], f4_msg(xv, foSV, en0, foEV));
            }
            {
                const float4 xv = *(const float4*)&nv[128 + c0];
                red4(&ov[128 + c0], f4_msg(xv, foSV, en1, foEV));
            }
            {
                const float4 xv = *(const float4*)&nv[256 + c0];
                red4(&ov[256 + c0], f4_msg(xv, foSV, en2, foEV));
            }
        }
    }
}

// ---------------------------------------------------------------------------
extern "C" void kernel_launch(void* const* d_in, const int* in_sizes, int n_in,
                              void* d_out, int out_size)
{
    const float* nss           = (const float*)d_in[0];
    const float* nsv           = (const float*)d_in[1];
    const float* edge_state    = (const float*)d_in[2];
    const float* edge_vector   = (const float*)d_in[3];
    const float* edge_distance = (const float*)d_in[4];
    const int*   edges         = (const int*)d_in[5];
    const float* W_filter      = (const float*)d_in[6];
    const float* b_filter      = (const float*)d_in[7];
    const float* W1            = (const float*)d_in[8];
    const float* b1            = (const float*)d_in[9];
    const float* W2            = (const float*)d_in[10];
    const float* b2            = (const float*)d_in[11];
    float* out = (float*)d_out;

    const int smem1 = (16384 + 2 * NB * 128) * sizeof(float);  // 128 KB
    cudaFuncSetAttribute(node_mlp, cudaFuncAttributeMaxDynamicSharedMemorySize, smem1);

    node_mlp<<<(NNODES + NB - 1) / NB, 256, smem1>>>(
        (const float4*)nss, (const float4*)nsv, W1, b1, W2, b2, (float4*)out);
    edge_kernel<<<1480, 128>>>(nss, nsv, edge_state, edge_vector, edge_distance,
                               edges, W_filter, b_filter, out);
}